// round 11
// baseline (speedup 1.0000x reference)
#include <cuda_runtime.h>
#include <cstdint>
#include <cstring>
#include <cmath>
#include <complex>

// =====================================================================
// TPe3nn: 6-path e3nn tensor product as (tiny CG contraction) + 4 GEMMs
//   T_p[uv][m] = alpha_p * sum_ij C[i,j,k] xa[b,u,i] xb[b,v,j],  m = k*128+b
//   out = T_p^T-contracted with streamed weight matrices (TF32 mma.sync)
// Weights (670 MB) are each read from DRAM exactly once (blocks partition N,
// each block owns the full M stripe). T tensors live in a device-global
// scratch and are served to all blocks from L2.
// =====================================================================

#define KDIM 4096   // uv dimension per path

// T scratch, layout T[uv][m] (m contiguous). 32 MB.
static __device__ float g_T[8388608];

#define OFF_T1 0        // 4096*128
#define OFF_T2 524288   // 4096*128
#define OFF_T3 1048576  // 4096*384
#define OFF_T4 2621440  // 4096*384
#define OFF_T5 4194304  // 4096*384
#define OFF_T6 5767168  // 4096*640

struct Coup {
    float w000;
    float w110[3][3];
    float w011[3][3];   // [j][k]
    float w101[3][3];   // [i][k]
    float w111[3][3][3];
    float w112[3][3][5];
    float s0, s1, s1e, s2e;
};

__device__ __forceinline__ unsigned f2tf32(float f) {
    unsigned u;
    asm("cvt.rna.tf32.f32 %0, %1;" : "=r"(u) : "f"(f));
    return u;
}

// ---------------------------------------------------------------------
// Phase A: build T tensors (TF32-rounded) from x1, x2
// ---------------------------------------------------------------------
__global__ void phaseA_kernel(const float* __restrict__ x1,
                              const float* __restrict__ x2, Coup c) {
    int t = blockIdx.x * blockDim.x + threadIdx.x;   // 4096*128 threads
    int b = t & 127;
    int uv = t >> 7;
    int u = uv >> 6, v = uv & 63;
    const float* xa = x1 + b * 256;
    const float* xb = x2 + b * 256;
    float a0 = xa[u];
    float b0 = xb[v];
    float a1[3], b1[3];
#pragma unroll
    for (int i = 0; i < 3; i++) a1[i] = xa[64 + u * 3 + i];
#pragma unroll
    for (int j = 0; j < 3; j++) b1[j] = xb[64 + v * 3 + j];

    unsigned* T = reinterpret_cast<unsigned*>(g_T);

    T[OFF_T1 + uv * 128 + b] = f2tf32(c.s0 * c.w000 * a0 * b0);

    float t2 = 0.f;
#pragma unroll
    for (int i = 0; i < 3; i++)
#pragma unroll
        for (int j = 0; j < 3; j++) t2 += c.w110[i][j] * a1[i] * b1[j];
    T[OFF_T2 + uv * 128 + b] = f2tf32(c.s0 * t2);

#pragma unroll
    for (int k = 0; k < 3; k++) {
        float s3 = 0.f, s4 = 0.f, s5 = 0.f;
#pragma unroll
        for (int j = 0; j < 3; j++) s3 += c.w011[j][k] * b1[j];
#pragma unroll
        for (int i = 0; i < 3; i++) s4 += c.w101[i][k] * a1[i];
#pragma unroll
        for (int i = 0; i < 3; i++)
#pragma unroll
            for (int j = 0; j < 3; j++) s5 += c.w111[i][j][k] * a1[i] * b1[j];
        T[OFF_T3 + uv * 384 + k * 128 + b] = f2tf32(c.s1 * a0 * s3);
        T[OFF_T4 + uv * 384 + k * 128 + b] = f2tf32(c.s1 * b0 * s4);
        T[OFF_T5 + uv * 384 + k * 128 + b] = f2tf32(c.s1e * s5);
    }
#pragma unroll
    for (int k = 0; k < 5; k++) {
        float s6 = 0.f;
#pragma unroll
        for (int i = 0; i < 3; i++)
#pragma unroll
            for (int j = 0; j < 3; j++) s6 += c.w112[i][j][k] * a1[i] * b1[j];
        T[OFF_T6 + uv * 640 + k * 128 + b] = f2tf32(c.s2e * s6);
    }
}

// ---------------------------------------------------------------------
// GEMM: D[m][n] = sum over paths p, k: T_p[k][m] * W_p[k][n]  (TF32 mma)
// One block owns the FULL M stripe for BN output columns -> each weight
// element is read from DRAM exactly once across the whole grid.
// Output: out[b*65536 + outBase + n*KOUT + k], b = m&127, k = m>>7.
// ---------------------------------------------------------------------
template <int MROWS, int BN, int NPATHS, int KOUT>
__global__ void __launch_bounds__(256, 1)
tp_gemm(const float* __restrict__ W0, const float* __restrict__ W1,
        const float* __restrict__ T0, const float* __restrict__ T1,
        float* __restrict__ out, int outBase, int ldw) {
    constexpr int BK = 16;
    constexpr int MP = MROWS + 4;   // padded to reduce LDS bank conflicts
    constexpr int BNP = BN + 4;
    constexpr int KTILES = KDIM / BK;           // 256
    constexpr int NTILES = NPATHS * KTILES;
    constexpr int LA = (BK * MROWS / 4) / 256;  // float4 per thread (A)
    constexpr int LB = (BK * BN) / 256;         // floats per thread (B)

    extern __shared__ float smem[];
    float* As = smem;                    // [2][BK][MP]
    float* Bs = smem + 2 * BK * MP;      // [2][BK][BNP]

    const int tid = threadIdx.x;
    const int n0 = blockIdx.x * BN;

    const int warp = tid >> 5, lane = tid & 31;
    const int wm = warp & 3, wn = warp >> 2;       // 4x2 warp grid
    constexpr int MW = MROWS / 4;                  // warp m extent
    constexpr int NWT = BN / 2;                    // warp n extent
    constexpr int MT = MW / 16;
    constexpr int NT = NWT / 8;
    const int g = lane >> 2, tg = lane & 3;        // groupID, tid-in-group

    float acc[MT][NT][4];
#pragma unroll
    for (int a = 0; a < MT; a++)
#pragma unroll
        for (int b = 0; b < NT; b++)
#pragma unroll
            for (int i = 0; i < 4; i++) acc[a][b][i] = 0.f;

    float rB[LB];

    // ---- prologue: tile 0 ----
    {
#pragma unroll
        for (int i = 0; i < LA; i++) {
            int e = tid + i * 256;
            int kk = e / (MROWS / 4);
            int mq = e - kk * (MROWS / 4);
            unsigned sa = (unsigned)__cvta_generic_to_shared(As + kk * MP + mq * 4);
            asm volatile("cp.async.cg.shared.global [%0], [%1], 16;\n"
                         :: "r"(sa), "l"(T0 + (size_t)kk * MROWS + mq * 4));
        }
        asm volatile("cp.async.commit_group;\n" ::: "memory");
#pragma unroll
        for (int i = 0; i < LB; i++) {
            int e = tid + i * 256;
            int kk = e / BN;
            int nn = e - kk * BN;
            rB[i] = __ldg(W0 + (size_t)kk * ldw + n0 + nn);
        }
    }

#pragma unroll 1
    for (int t = 0; t < NTILES; ++t) {
        asm volatile("cp.async.wait_group 0;\n" ::: "memory");
        __syncthreads();

        // prefetch next A tile into the other stage
        if (t + 1 < NTILES) {
            int tn = t + 1;
            const float* Tp = (NPATHS == 2 && tn >= KTILES) ? T1 : T0;
            int k0 = (tn & (KTILES - 1)) * BK;
            const float* src = Tp + (size_t)k0 * MROWS;
            float* dstBase = As + (tn & 1) * (BK * MP);
#pragma unroll
            for (int i = 0; i < LA; i++) {
                int e = tid + i * 256;
                int kk = e / (MROWS / 4);
                int mq = e - kk * (MROWS / 4);
                unsigned sa = (unsigned)__cvta_generic_to_shared(dstBase + kk * MP + mq * 4);
                asm volatile("cp.async.cg.shared.global [%0], [%1], 16;\n"
                             :: "r"(sa), "l"(src + (size_t)kk * MROWS + mq * 4));
            }
            asm volatile("cp.async.commit_group;\n" ::: "memory");
        }

        // store B regs (TF32-rounded) to smem
        {
            float* dstBase = Bs + (t & 1) * (BK * BNP);
#pragma unroll
            for (int i = 0; i < LB; i++) {
                int e = tid + i * 256;
                int kk = e / BN;
                int nn = e - kk * BN;
                dstBase[kk * BNP + nn] = __uint_as_float(f2tf32(rB[i]));
            }
        }
        __syncthreads();

        // issue next B loads early (retire under compute)
        if (t + 1 < NTILES) {
            int tn = t + 1;
            const float* Wp = (NPATHS == 2 && tn >= KTILES) ? W1 : W0;
            int k0 = (tn & (KTILES - 1)) * BK;
#pragma unroll
            for (int i = 0; i < LB; i++) {
                int e = tid + i * 256;
                int kk = e / BN;
                int nn = e - kk * BN;
                rB[i] = __ldg(Wp + (size_t)(k0 + kk) * ldw + n0 + nn);
            }
        }

        // compute
        const float* A = As + (t & 1) * (BK * MP);
        const float* B = Bs + (t & 1) * (BK * BNP);
#pragma unroll
        for (int kk = 0; kk < BK; kk += 8) {
            uint32_t bf[NT][2];
#pragma unroll
            for (int nt = 0; nt < NT; nt++) {
                int col = wn * NWT + nt * 8 + g;
                bf[nt][0] = __float_as_uint(B[(kk + tg) * BNP + col]);
                bf[nt][1] = __float_as_uint(B[(kk + tg + 4) * BNP + col]);
            }
#pragma unroll
            for (int mt = 0; mt < MT; mt++) {
                int row = wm * MW + mt * 16 + g;
                uint32_t fa0 = __float_as_uint(A[(kk + tg) * MP + row]);
                uint32_t fa1 = __float_as_uint(A[(kk + tg) * MP + row + 8]);
                uint32_t fa2 = __float_as_uint(A[(kk + tg + 4) * MP + row]);
                uint32_t fa3 = __float_as_uint(A[(kk + tg + 4) * MP + row + 8]);
#pragma unroll
                for (int nt = 0; nt < NT; nt++) {
                    asm volatile(
                        "mma.sync.aligned.m16n8k8.row.col.f32.tf32.tf32.f32 "
                        "{%0,%1,%2,%3}, {%4,%5,%6,%7}, {%8,%9}, {%0,%1,%2,%3};\n"
                        : "+f"(acc[mt][nt][0]), "+f"(acc[mt][nt][1]),
                          "+f"(acc[mt][nt][2]), "+f"(acc[mt][nt][3])
                        : "r"(fa0), "r"(fa1), "r"(fa2), "r"(fa3),
                          "r"(bf[nt][0]), "r"(bf[nt][1]));
                }
            }
        }
    }

    // ---- epilogue ----
#pragma unroll
    for (int mt = 0; mt < MT; mt++) {
#pragma unroll
        for (int half = 0; half < 2; half++) {
            int m = wm * MW + mt * 16 + g + half * 8;
            int b = m & 127;
            int k = m >> 7;
            size_t base = (size_t)b * 65536 + (size_t)outBase + (size_t)k;
#pragma unroll
            for (int nt = 0; nt < NT; nt++) {
                int n = n0 + wn * NWT + nt * 8 + 2 * tg;
                out[base + (size_t)n * KOUT] = acc[mt][nt][half * 2 + 0];
                out[base + (size_t)(n + 1) * KOUT] = acc[mt][nt][half * 2 + 1];
            }
        }
    }
}

// ---------------------------------------------------------------------
// Host: exact replica of the reference CG / real-basis math (fp64)
// ---------------------------------------------------------------------
static double factd(int n) { double r = 1.0; for (int i = 2; i <= n; i++) r *= i; return r; }

static void cg_complex_host(int l1, int l2, int l3, double* C) {
    int d1 = 2 * l1 + 1, d2 = 2 * l2 + 1, d3 = 2 * l3 + 1;
    for (int i = 0; i < d1 * d2 * d3; i++) C[i] = 0.0;
    for (int m1 = -l1; m1 <= l1; m1++)
        for (int m2 = -l2; m2 <= l2; m2++) {
            int m3 = m1 + m2;
            if (m3 < -l3 || m3 > l3) continue;
            double pref = std::sqrt((2 * l3 + 1) * factd(l3 + l1 - l2) * factd(l3 - l1 + l2) *
                                    factd(l1 + l2 - l3) / factd(l1 + l2 + l3 + 1));
            pref *= std::sqrt(factd(l3 + m3) * factd(l3 - m3) * factd(l1 - m1) *
                              factd(l1 + m1) * factd(l2 - m2) * factd(l2 + m2));
            double s = 0.0;
            for (int k = 0; k <= l1 + l2 - l3; k++) {
                int d[5] = {l1 + l2 - l3 - k, l1 - m1 - k, l2 + m2 - k,
                            l3 - l2 + m1 + k, l3 - l1 - m2 + k};
                bool ok = true;
                for (int q = 0; q < 5; q++) if (d[q] < 0) ok = false;
                if (!ok) continue;
                double den = factd(k);
                for (int q = 0; q < 5; q++) den *= factd(d[q]);
                s += ((k & 1) ? -1.0 : 1.0) / den;
            }
            C[((m1 + l1) * d2 + (m2 + l2)) * d3 + (m3 + l3)] = pref * s;
        }
}

static void real_basis_host(int l, std::complex<double>* U) {
    int d = 2 * l + 1;
    for (int i = 0; i < d * d; i++) U[i] = 0.0;
    double s2 = 1.0 / std::sqrt(2.0);
    for (int m = -l; m <= l; m++) {
        int r = m + l;
        if (m > 0) {
            U[r * d + (-m + l)] = s2;
            U[r * d + (m + l)] = ((m & 1) ? -1.0 : 1.0) * s2;
        } else if (m == 0) {
            U[r * d + l] = 1.0;
        } else {
            int a = -m;
            U[r * d + (-a + l)] = std::complex<double>(0.0, s2);
            U[r * d + (a + l)] = std::complex<double>(0.0, -(((a & 1) ? -1.0 : 1.0) * s2));
        }
    }
}

static void w3j_host(int l1, int l2, int l3, float* out) {
    int d1 = 2 * l1 + 1, d2 = 2 * l2 + 1, d3 = 2 * l3 + 1;
    double Cc[125];
    cg_complex_host(l1, l2, l3, Cc);
    std::complex<double> U1[25], U2[25], U3[25];
    real_basis_host(l1, U1); real_basis_host(l2, U2); real_basis_host(l3, U3);
    double Cr[125], Ci[125];
    for (int i = 0; i < d1; i++)
        for (int j = 0; j < d2; j++)
            for (int k = 0; k < d3; k++) {
                std::complex<double> acc(0.0, 0.0);
                for (int m = 0; m < d1; m++)
                    for (int n = 0; n < d2; n++)
                        for (int p = 0; p < d3; p++)
                            acc += U1[i * d1 + m] * U2[j * d2 + n] *
                                   std::conj(U3[k * d3 + p]) * Cc[(m * d2 + n) * d3 + p];
                Cr[(i * d2 + j) * d3 + k] = acc.real();
                Ci[(i * d2 + j) * d3 + k] = acc.imag();
            }
    double nr = 0.0, ni = 0.0;
    int tot = d1 * d2 * d3;
    for (int i = 0; i < tot; i++) { nr += Cr[i] * Cr[i]; ni += Ci[i] * Ci[i]; }
    const double* S = (nr >= ni) ? Cr : Ci;
    double nn = std::sqrt((nr >= ni) ? nr : ni);
    for (int i = 0; i < tot; i++) out[i] = (float)(S[i] / nn);
}

// ---------------------------------------------------------------------
extern "C" void kernel_launch(void* const* d_in, const int* in_sizes, int n_in,
                              void* d_out, int out_size) {
    const float* x1 = (const float*)d_in[0];
    const float* x2 = (const float*)d_in[1];
    const float* w1 = (const float*)d_in[2];
    const float* w2 = (const float*)d_in[3];
    const float* w3 = (const float*)d_in[4];
    const float* w4 = (const float*)d_in[5];
    const float* w5 = (const float*)d_in[6];
    const float* w6 = (const float*)d_in[7];
    float* out = (float*)d_out;

    Coup c;
    float tmp[64];
    w3j_host(0, 0, 0, tmp); c.w000 = tmp[0];
    w3j_host(1, 1, 0, tmp); memcpy(c.w110, tmp, 9 * sizeof(float));
    w3j_host(0, 1, 1, tmp); memcpy(c.w011, tmp, 9 * sizeof(float));
    w3j_host(1, 0, 1, tmp); memcpy(c.w101, tmp, 9 * sizeof(float));
    w3j_host(1, 1, 1, tmp); memcpy(c.w111, tmp, 27 * sizeof(float));
    w3j_host(1, 1, 2, tmp); memcpy(c.w112, tmp, 45 * sizeof(float));
    c.s0 = sqrtf(1.0f / 8192.0f);
    c.s1 = sqrtf(3.0f / 8192.0f);
    c.s1e = sqrtf(3.0f / 4096.0f);
    c.s2e = sqrtf(5.0f / 4096.0f);

    float* T = nullptr;
    cudaGetSymbolAddress((void**)&T, g_T);

    cudaFuncSetAttribute((const void*)tp_gemm<128, 64, 2, 1>,
                         cudaFuncAttributeMaxDynamicSharedMemorySize, 25600);
    cudaFuncSetAttribute((const void*)tp_gemm<384, 64, 2, 3>,
                         cudaFuncAttributeMaxDynamicSharedMemorySize, 58368);
    cudaFuncSetAttribute((const void*)tp_gemm<384, 32, 1, 3>,
                         cudaFuncAttributeMaxDynamicSharedMemorySize, 54272);
    cudaFuncSetAttribute((const void*)tp_gemm<640, 32, 1, 5>,
                         cudaFuncAttributeMaxDynamicSharedMemorySize, 87040);

    phaseA_kernel<<<2048, 256>>>(x1, x2, c);

    // G0: o0 (b, 8192x0e) at offset 0
    tp_gemm<128, 64, 2, 1><<<128, 256, 25600>>>(w1, w2, T + OFF_T1, T + OFF_T2, out, 0, 8192);
    // G1: o1 (b, 8192x1o) at offset 8192
    tp_gemm<384, 64, 2, 3><<<128, 256, 58368>>>(w3, w4, T + OFF_T3, T + OFF_T4, out, 8192, 8192);
    // G2: o1e (b, 4096x1e) at offset 32768
    tp_gemm<384, 32, 1, 3><<<128, 256, 54272>>>(w5, w5, T + OFF_T5, T + OFF_T5, out, 32768, 4096);
    // G3: o2e (b, 4096x2e) at offset 45056
    tp_gemm<640, 32, 1, 5><<<128, 256, 87040>>>(w6, w6, T + OFF_T6, T + OFF_T6, out, 45056, 4096);
}

// round 12
// speedup vs baseline: 1.6821x; 1.6821x over previous
#include <cuda_runtime.h>
#include <cstdint>
#include <cstring>
#include <cmath>
#include <complex>

// =====================================================================
// TPe3nn: 6-path e3nn tensor product as (tiny CG contraction) + 4 GEMMs
//   T_p[uv][m] = alpha_p * sum_ij C[i,j,k] xa[b,u,i] xb[b,v,j],  m = k*128+b
//   out = T_p^T-contracted with streamed weight matrices (TF32 mma.sync)
// R11 fix: B (weights) was latency-bound (2KB in flight/CTA -> 303GB/s DRAM).
// Now both A and B stream through a multi-stage cp.async ring (STAGES
// templated per kernel), one __syncthreads per tile, conflict-free smem.
// =====================================================================

#define KDIM 4096   // uv dimension per path

// T scratch, layout T[uv][m] (m contiguous). 32 MB.
static __device__ float g_T[8388608];

#define OFF_T1 0        // 4096*128
#define OFF_T2 524288   // 4096*128
#define OFF_T3 1048576  // 4096*384
#define OFF_T4 2621440  // 4096*384
#define OFF_T5 4194304  // 4096*384
#define OFF_T6 5767168  // 4096*640

struct Coup {
    float w000;
    float w110[3][3];
    float w011[3][3];   // [j][k]
    float w101[3][3];   // [i][k]
    float w111[3][3][3];
    float w112[3][3][5];
    float s0, s1, s1e, s2e;
};

__device__ __forceinline__ unsigned f2tf32(float f) {
    unsigned u;
    asm("cvt.rna.tf32.f32 %0, %1;" : "=r"(u) : "f"(f));
    return u;
}

// ---------------------------------------------------------------------
// Phase A: build T tensors (TF32-rounded) from x1, x2
// ---------------------------------------------------------------------
__global__ void phaseA_kernel(const float* __restrict__ x1,
                              const float* __restrict__ x2, Coup c) {
    int t = blockIdx.x * blockDim.x + threadIdx.x;   // 4096*128 threads
    int b = t & 127;
    int uv = t >> 7;
    int u = uv >> 6, v = uv & 63;
    const float* xa = x1 + b * 256;
    const float* xb = x2 + b * 256;
    float a0 = xa[u];
    float b0 = xb[v];
    float a1[3], b1[3];
#pragma unroll
    for (int i = 0; i < 3; i++) a1[i] = xa[64 + u * 3 + i];
#pragma unroll
    for (int j = 0; j < 3; j++) b1[j] = xb[64 + v * 3 + j];

    unsigned* T = reinterpret_cast<unsigned*>(g_T);

    T[OFF_T1 + uv * 128 + b] = f2tf32(c.s0 * c.w000 * a0 * b0);

    float t2 = 0.f;
#pragma unroll
    for (int i = 0; i < 3; i++)
#pragma unroll
        for (int j = 0; j < 3; j++) t2 += c.w110[i][j] * a1[i] * b1[j];
    T[OFF_T2 + uv * 128 + b] = f2tf32(c.s0 * t2);

#pragma unroll
    for (int k = 0; k < 3; k++) {
        float s3 = 0.f, s4 = 0.f, s5 = 0.f;
#pragma unroll
        for (int j = 0; j < 3; j++) s3 += c.w011[j][k] * b1[j];
#pragma unroll
        for (int i = 0; i < 3; i++) s4 += c.w101[i][k] * a1[i];
#pragma unroll
        for (int i = 0; i < 3; i++)
#pragma unroll
            for (int j = 0; j < 3; j++) s5 += c.w111[i][j][k] * a1[i] * b1[j];
        T[OFF_T3 + uv * 384 + k * 128 + b] = f2tf32(c.s1 * a0 * s3);
        T[OFF_T4 + uv * 384 + k * 128 + b] = f2tf32(c.s1 * b0 * s4);
        T[OFF_T5 + uv * 384 + k * 128 + b] = f2tf32(c.s1e * s5);
    }
#pragma unroll
    for (int k = 0; k < 5; k++) {
        float s6 = 0.f;
#pragma unroll
        for (int i = 0; i < 3; i++)
#pragma unroll
            for (int j = 0; j < 3; j++) s6 += c.w112[i][j][k] * a1[i] * b1[j];
        T[OFF_T6 + uv * 640 + k * 128 + b] = f2tf32(c.s2e * s6);
    }
}

// ---------------------------------------------------------------------
// GEMM: D[m][n] = sum over paths p, k: T_p[k][m] * W_p[k][n]  (TF32 mma)
// One block owns the FULL M stripe for BN output columns -> each weight
// element is read from DRAM exactly once across the whole grid.
// Multi-stage cp.async ring for BOTH A (from L2) and B (from DRAM).
// Output: out[b*65536 + outBase + n*KOUT + k], b = m&127, k = m>>7.
// ---------------------------------------------------------------------
template <int MROWS, int BN, int NPATHS, int KOUT, int STAGES>
__global__ void __launch_bounds__(256, 1)
tp_gemm(const float* __restrict__ W0, const float* __restrict__ W1,
        const float* __restrict__ T0, const float* __restrict__ T1,
        float* __restrict__ out, int outBase, int ldw) {
    constexpr int BK = 16;
    constexpr int MP = MROWS + 8;   // pitch: conflict-free (mod 32 = 8) + 16B-aligned
    constexpr int BNP = BN + 8;
    constexpr int KTILES = KDIM / BK;           // 256
    constexpr int NTILES = NPATHS * KTILES;
    constexpr int LA = (BK * MROWS / 4) / 256;  // float4 per thread (A); exact
    constexpr int NB4 = BK * BN / 4;            // float4 per stage (B): 256 or 128

    extern __shared__ float smem[];
    float* As = smem;                           // [STAGES][BK][MP]
    float* Bs = smem + STAGES * BK * MP;        // [STAGES][BK][BNP]

    const int tid = threadIdx.x;
    const int n0 = blockIdx.x * BN;

    const int warp = tid >> 5, lane = tid & 31;
    const int wm = warp & 3, wn = warp >> 2;       // 4x2 warp grid
    constexpr int MW = MROWS / 4;                  // warp m extent
    constexpr int NWT = BN / 2;                    // warp n extent
    constexpr int MT = MW / 16;
    constexpr int NT = NWT / 8;
    const int g = lane >> 2, tg = lane & 3;        // groupID, tid-in-group

    float acc[MT][NT][4];
#pragma unroll
    for (int a = 0; a < MT; a++)
#pragma unroll
        for (int b = 0; b < NT; b++)
#pragma unroll
            for (int i = 0; i < 4; i++) acc[a][b][i] = 0.f;

    // issue cp.async loads (A tile from T, B tile from W) for tile tn
    auto issue_tile = [&](int tn) {
        const float* Tp = (NPATHS == 2 && tn >= KTILES) ? T1 : T0;
        const float* Wp = (NPATHS == 2 && tn >= KTILES) ? W1 : W0;
        int k0 = (tn & (KTILES - 1)) * BK;
        int st = tn % STAGES;
        float* Ad = As + st * (BK * MP);
        float* Bd = Bs + st * (BK * BNP);
        const float* Asrc = Tp + (size_t)k0 * MROWS;
#pragma unroll
        for (int i = 0; i < LA; i++) {
            int e = tid + i * 256;
            int kk = e / (MROWS / 4);
            int mq = e - kk * (MROWS / 4);
            unsigned sa = (unsigned)__cvta_generic_to_shared(Ad + kk * MP + mq * 4);
            asm volatile("cp.async.cg.shared.global [%0], [%1], 16;\n"
                         :: "r"(sa), "l"(Asrc + (size_t)kk * MROWS + mq * 4));
        }
        if (NB4 >= 256) {
#pragma unroll
            for (int i = 0; i < NB4 / 256; i++) {
                int e = tid + i * 256;
                int kk = e / (BN / 4);
                int j = e - kk * (BN / 4);
                unsigned sb = (unsigned)__cvta_generic_to_shared(Bd + kk * BNP + j * 4);
                asm volatile("cp.async.cg.shared.global [%0], [%1], 16;\n"
                             :: "r"(sb), "l"(Wp + (size_t)(k0 + kk) * ldw + n0 + j * 4));
            }
        } else {
            if (tid < NB4) {
                int kk = tid / (BN / 4);
                int j = tid - kk * (BN / 4);
                unsigned sb = (unsigned)__cvta_generic_to_shared(Bd + kk * BNP + j * 4);
                asm volatile("cp.async.cg.shared.global [%0], [%1], 16;\n"
                             :: "r"(sb), "l"(Wp + (size_t)(k0 + kk) * ldw + n0 + j * 4));
            }
        }
        asm volatile("cp.async.commit_group;\n" ::: "memory");
    };

    // ---- prologue: fill STAGES-1 stages ----
#pragma unroll
    for (int s = 0; s < STAGES - 1; ++s) issue_tile(s);

#pragma unroll 1
    for (int t = 0; t < NTILES; ++t) {
        // tile t arrived (<= STAGES-2 groups still pending)
        asm volatile("cp.async.wait_group %0;\n" :: "n"(STAGES - 2) : "memory");
        // joint barrier: tile t visible to all warps AND all warps done
        // computing tile t-1 (whose stage is about to be overwritten)
        __syncthreads();

        if (t + STAGES - 1 < NTILES) issue_tile(t + STAGES - 1);

        const float* A = As + (t % STAGES) * (BK * MP);
        const float* B = Bs + (t % STAGES) * (BK * BNP);
#pragma unroll
        for (int kk = 0; kk < BK; kk += 8) {
            uint32_t bf[NT][2];
#pragma unroll
            for (int nt = 0; nt < NT; nt++) {
                int col = wn * NWT + nt * 8 + g;
                bf[nt][0] = f2tf32(B[(kk + tg) * BNP + col]);
                bf[nt][1] = f2tf32(B[(kk + tg + 4) * BNP + col]);
            }
#pragma unroll
            for (int mt = 0; mt < MT; mt++) {
                int row = wm * MW + mt * 16 + g;
                uint32_t fa0 = __float_as_uint(A[(kk + tg) * MP + row]);
                uint32_t fa1 = __float_as_uint(A[(kk + tg) * MP + row + 8]);
                uint32_t fa2 = __float_as_uint(A[(kk + tg + 4) * MP + row]);
                uint32_t fa3 = __float_as_uint(A[(kk + tg + 4) * MP + row + 8]);
#pragma unroll
                for (int nt = 0; nt < NT; nt++) {
                    asm volatile(
                        "mma.sync.aligned.m16n8k8.row.col.f32.tf32.tf32.f32 "
                        "{%0,%1,%2,%3}, {%4,%5,%6,%7}, {%8,%9}, {%0,%1,%2,%3};\n"
                        : "+f"(acc[mt][nt][0]), "+f"(acc[mt][nt][1]),
                          "+f"(acc[mt][nt][2]), "+f"(acc[mt][nt][3])
                        : "r"(fa0), "r"(fa1), "r"(fa2), "r"(fa3),
                          "r"(bf[nt][0]), "r"(bf[nt][1]));
                }
            }
        }
    }

    // ---- epilogue ----
#pragma unroll
    for (int mt = 0; mt < MT; mt++) {
#pragma unroll
        for (int half = 0; half < 2; half++) {
            int m = wm * MW + mt * 16 + g + half * 8;
            int b = m & 127;
            int k = m >> 7;
            size_t base = (size_t)b * 65536 + (size_t)outBase + (size_t)k;
#pragma unroll
            for (int nt = 0; nt < NT; nt++) {
                int n = n0 + wn * NWT + nt * 8 + 2 * tg;
                out[base + (size_t)n * KOUT] = acc[mt][nt][half * 2 + 0];
                out[base + (size_t)(n + 1) * KOUT] = acc[mt][nt][half * 2 + 1];
            }
        }
    }
}

// ---------------------------------------------------------------------
// Host: exact replica of the reference CG / real-basis math (fp64)
// ---------------------------------------------------------------------
static double factd(int n) { double r = 1.0; for (int i = 2; i <= n; i++) r *= i; return r; }

static void cg_complex_host(int l1, int l2, int l3, double* C) {
    int d1 = 2 * l1 + 1, d2 = 2 * l2 + 1, d3 = 2 * l3 + 1;
    for (int i = 0; i < d1 * d2 * d3; i++) C[i] = 0.0;
    for (int m1 = -l1; m1 <= l1; m1++)
        for (int m2 = -l2; m2 <= l2; m2++) {
            int m3 = m1 + m2;
            if (m3 < -l3 || m3 > l3) continue;
            double pref = std::sqrt((2 * l3 + 1) * factd(l3 + l1 - l2) * factd(l3 - l1 + l2) *
                                    factd(l1 + l2 - l3) / factd(l1 + l2 + l3 + 1));
            pref *= std::sqrt(factd(l3 + m3) * factd(l3 - m3) * factd(l1 - m1) *
                              factd(l1 + m1) * factd(l2 - m2) * factd(l2 + m2));
            double s = 0.0;
            for (int k = 0; k <= l1 + l2 - l3; k++) {
                int d[5] = {l1 + l2 - l3 - k, l1 - m1 - k, l2 + m2 - k,
                            l3 - l2 + m1 + k, l3 - l1 - m2 + k};
                bool ok = true;
                for (int q = 0; q < 5; q++) if (d[q] < 0) ok = false;
                if (!ok) continue;
                double den = factd(k);
                for (int q = 0; q < 5; q++) den *= factd(d[q]);
                s += ((k & 1) ? -1.0 : 1.0) / den;
            }
            C[((m1 + l1) * d2 + (m2 + l2)) * d3 + (m3 + l3)] = pref * s;
        }
}

static void real_basis_host(int l, std::complex<double>* U) {
    int d = 2 * l + 1;
    for (int i = 0; i < d * d; i++) U[i] = 0.0;
    double s2 = 1.0 / std::sqrt(2.0);
    for (int m = -l; m <= l; m++) {
        int r = m + l;
        if (m > 0) {
            U[r * d + (-m + l)] = s2;
            U[r * d + (m + l)] = ((m & 1) ? -1.0 : 1.0) * s2;
        } else if (m == 0) {
            U[r * d + l] = 1.0;
        } else {
            int a = -m;
            U[r * d + (-a + l)] = std::complex<double>(0.0, s2);
            U[r * d + (a + l)] = std::complex<double>(0.0, -(((a & 1) ? -1.0 : 1.0) * s2));
        }
    }
}

static void w3j_host(int l1, int l2, int l3, float* out) {
    int d1 = 2 * l1 + 1, d2 = 2 * l2 + 1, d3 = 2 * l3 + 1;
    double Cc[125];
    cg_complex_host(l1, l2, l3, Cc);
    std::complex<double> U1[25], U2[25], U3[25];
    real_basis_host(l1, U1); real_basis_host(l2, U2); real_basis_host(l3, U3);
    double Cr[125], Ci[125];
    for (int i = 0; i < d1; i++)
        for (int j = 0; j < d2; j++)
            for (int k = 0; k < d3; k++) {
                std::complex<double> acc(0.0, 0.0);
                for (int m = 0; m < d1; m++)
                    for (int n = 0; n < d2; n++)
                        for (int p = 0; p < d3; p++)
                            acc += U1[i * d1 + m] * U2[j * d2 + n] *
                                   std::conj(U3[k * d3 + p]) * Cc[(m * d2 + n) * d3 + p];
                Cr[(i * d2 + j) * d3 + k] = acc.real();
                Ci[(i * d2 + j) * d3 + k] = acc.imag();
            }
    double nr = 0.0, ni = 0.0;
    int tot = d1 * d2 * d3;
    for (int i = 0; i < tot; i++) { nr += Cr[i] * Cr[i]; ni += Ci[i] * Ci[i]; }
    const double* S = (nr >= ni) ? Cr : Ci;
    double nn = std::sqrt((nr >= ni) ? nr : ni);
    for (int i = 0; i < tot; i++) out[i] = (float)(S[i] / nn);
}

// ---------------------------------------------------------------------
extern "C" void kernel_launch(void* const* d_in, const int* in_sizes, int n_in,
                              void* d_out, int out_size) {
    const float* x1 = (const float*)d_in[0];
    const float* x2 = (const float*)d_in[1];
    const float* w1 = (const float*)d_in[2];
    const float* w2 = (const float*)d_in[3];
    const float* w3 = (const float*)d_in[4];
    const float* w4 = (const float*)d_in[5];
    const float* w5 = (const float*)d_in[6];
    const float* w6 = (const float*)d_in[7];
    float* out = (float*)d_out;

    Coup c;
    float tmp[64];
    w3j_host(0, 0, 0, tmp); c.w000 = tmp[0];
    w3j_host(1, 1, 0, tmp); memcpy(c.w110, tmp, 9 * sizeof(float));
    w3j_host(0, 1, 1, tmp); memcpy(c.w011, tmp, 9 * sizeof(float));
    w3j_host(1, 0, 1, tmp); memcpy(c.w101, tmp, 9 * sizeof(float));
    w3j_host(1, 1, 1, tmp); memcpy(c.w111, tmp, 27 * sizeof(float));
    w3j_host(1, 1, 2, tmp); memcpy(c.w112, tmp, 45 * sizeof(float));
    c.s0 = sqrtf(1.0f / 8192.0f);
    c.s1 = sqrtf(3.0f / 8192.0f);
    c.s1e = sqrtf(3.0f / 4096.0f);
    c.s2e = sqrtf(5.0f / 4096.0f);

    float* T = nullptr;
    cudaGetSymbolAddress((void**)&T, g_T);

    // smem bytes: STAGES * 16 * (MP + BNP) * 4
    constexpr int SM_G0 = 8 * 16 * (136 + 72) * 4;   // 106496
    constexpr int SM_G1 = 6 * 16 * (392 + 72) * 4;   // 178176
    constexpr int SM_G2 = 6 * 16 * (392 + 40) * 4;   // 165888
    constexpr int SM_G3 = 4 * 16 * (648 + 40) * 4;   // 176128

    cudaFuncSetAttribute((const void*)tp_gemm<128, 64, 2, 1, 8>,
                         cudaFuncAttributeMaxDynamicSharedMemorySize, SM_G0);
    cudaFuncSetAttribute((const void*)tp_gemm<384, 64, 2, 3, 6>,
                         cudaFuncAttributeMaxDynamicSharedMemorySize, SM_G1);
    cudaFuncSetAttribute((const void*)tp_gemm<384, 32, 1, 3, 6>,
                         cudaFuncAttributeMaxDynamicSharedMemorySize, SM_G2);
    cudaFuncSetAttribute((const void*)tp_gemm<640, 32, 1, 5, 4>,
                         cudaFuncAttributeMaxDynamicSharedMemorySize, SM_G3);

    phaseA_kernel<<<2048, 256>>>(x1, x2, c);

    // G0: o0 (b, 8192x0e) at offset 0
    tp_gemm<128, 64, 2, 1, 8><<<128, 256, SM_G0>>>(w1, w2, T + OFF_T1, T + OFF_T2, out, 0, 8192);
    // G1: o1 (b, 8192x1o) at offset 8192
    tp_gemm<384, 64, 2, 3, 6><<<128, 256, SM_G1>>>(w3, w4, T + OFF_T3, T + OFF_T4, out, 8192, 8192);
    // G2: o1e (b, 4096x1e) at offset 32768
    tp_gemm<384, 32, 1, 3, 6><<<128, 256, SM_G2>>>(w5, w5, T + OFF_T5, T + OFF_T5, out, 32768, 4096);
    // G3: o2e (b, 4096x2e) at offset 45056
    tp_gemm<640, 32, 1, 5, 4><<<128, 256, SM_G3>>>(w6, w6, T + OFF_T6, T + OFF_T6, out, 45056, 4096);
}

// round 17
// speedup vs baseline: 1.7990x; 1.0695x over previous
#include <cuda_runtime.h>
#include <cstdint>
#include <cstring>
#include <cmath>
#include <complex>

// =====================================================================
// TPe3nn: 6-path e3nn tensor product as (tiny CG contraction) + 4 GEMMs
// R12 fix: mainloop was issue-bound (48 scalar A-LDS vs 24 MMA per tile).
// A is now stored in g_T pre-swizzled per 16k-tile so each lane's 4-reg
// mma fragment is ONE ld.shared.v4 (bank-conflict-free via g^2tg), and
// the A cp.async is a contiguous tile copy. Deeper rings (12/7/8/5).
// =====================================================================

#define KDIM 4096   // uv dimension per path

// T scratch, swizzled per-tile layout. 32 MB.
static __device__ float g_T[8388608];

#define OFF_T1 0        // 4096*128
#define OFF_T2 524288   // 4096*128
#define OFF_T3 1048576  // 4096*384
#define OFF_T4 2621440  // 4096*384
#define OFF_T5 4194304  // 4096*384
#define OFF_T6 5767168  // 4096*640

struct Coup {
    float w000;
    float w110[3][3];
    float w011[3][3];   // [j][k]
    float w101[3][3];   // [i][k]
    float w111[3][3][3];
    float w112[3][3][5];
    float s0, s1, s1e, s2e;
};

__device__ __forceinline__ unsigned f2tf32(float f) {
    unsigned u;
    asm("cvt.rna.tf32.f32 %0, %1;" : "=r"(u) : "f"(f));
    return u;
}

// ---------------------------------------------------------------------
// Phase A: build T tensors (TF32-rounded, swizzled layout) from x1, x2
// Tile layout (per 16k x MROWS tile, NM16 = MROWS/16):
//   element (k, m):  h=k>>3, tg=k&3, kb=(k>>2)&1, mb16=m>>4, g=m&7, mbit=(m>>3)&1
//   idx = (((h*4+tg)*NM16 + mb16)*8 + (g ^ (tg<<1)))*4 + kb*2 + mbit
// so lane (g,tg) reads its full mma A-fragment as one float4.
// ---------------------------------------------------------------------
__global__ void phaseA_kernel(const float* __restrict__ x1,
                              const float* __restrict__ x2, Coup c) {
    int t = blockIdx.x * blockDim.x + threadIdx.x;   // 4096*128 threads
    int b = t & 127;
    int uv = t >> 7;
    int u = uv >> 6, v = uv & 63;
    const float* xa = x1 + b * 256;
    const float* xb = x2 + b * 256;
    float a0 = xa[u];
    float b0 = xb[v];
    float a1[3], b1[3];
#pragma unroll
    for (int i = 0; i < 3; i++) a1[i] = xa[64 + u * 3 + i];
#pragma unroll
    for (int j = 0; j < 3; j++) b1[j] = xb[64 + v * 3 + j];

    // swizzle components (uv is the contraction index k; b defines m bits)
    int tile = uv >> 4;
    int kt = uv & 15;
    int tgk = kt & 3, h = kt >> 3, kb = (kt >> 2) & 1;
    int h4tg = h * 4 + tgk;
    int gx = (b & 7) ^ (tgk << 1);
    int mbit = (b >> 3) & 1;
    int bhi = b >> 4;
    int kbm = kb * 2 + mbit;

    unsigned* T = reinterpret_cast<unsigned*>(g_T);

    // KOUT=1 paths (NM16=8, tile size 2048): m = b
    {
        int idx = ((h4tg * 8 + bhi) * 8 + gx) * 4 + kbm;
        T[OFF_T1 + tile * 2048 + idx] = f2tf32(c.s0 * c.w000 * a0 * b0);
        float t2 = 0.f;
#pragma unroll
        for (int i = 0; i < 3; i++)
#pragma unroll
            for (int j = 0; j < 3; j++) t2 += c.w110[i][j] * a1[i] * b1[j];
        T[OFF_T2 + tile * 2048 + idx] = f2tf32(c.s0 * t2);
    }

    // KOUT=3 paths (NM16=24, tile size 6144): m = k*128 + b
#pragma unroll
    for (int k = 0; k < 3; k++) {
        float s3 = 0.f, s4 = 0.f, s5 = 0.f;
#pragma unroll
        for (int j = 0; j < 3; j++) s3 += c.w011[j][k] * b1[j];
#pragma unroll
        for (int i = 0; i < 3; i++) s4 += c.w101[i][k] * a1[i];
#pragma unroll
        for (int i = 0; i < 3; i++)
#pragma unroll
            for (int j = 0; j < 3; j++) s5 += c.w111[i][j][k] * a1[i] * b1[j];
        int idx = ((h4tg * 24 + k * 8 + bhi) * 8 + gx) * 4 + kbm;
        T[OFF_T3 + tile * 6144 + idx] = f2tf32(c.s1 * a0 * s3);
        T[OFF_T4 + tile * 6144 + idx] = f2tf32(c.s1 * b0 * s4);
        T[OFF_T5 + tile * 6144 + idx] = f2tf32(c.s1e * s5);
    }
    // KOUT=5 path (NM16=40, tile size 10240)
#pragma unroll
    for (int k = 0; k < 5; k++) {
        float s6 = 0.f;
#pragma unroll
        for (int i = 0; i < 3; i++)
#pragma unroll
            for (int j = 0; j < 3; j++) s6 += c.w112[i][j][k] * a1[i] * b1[j];
        int idx = ((h4tg * 40 + k * 8 + bhi) * 8 + gx) * 4 + kbm;
        T[OFF_T6 + tile * 10240 + idx] = f2tf32(c.s2e * s6);
    }
}

// ---------------------------------------------------------------------
// GEMM: D[m][n] = sum over paths p, k: T_p[k][m] * W_p[k][n]  (TF32 mma)
// A tiles are pre-swizzled in g_T -> contiguous cp.async copy + v4 LDS.
// Output: out[b*65536 + outBase + n*KOUT + k], b = m&127, k = m>>7.
// ---------------------------------------------------------------------
template <int MROWS, int BN, int NPATHS, int KOUT, int STAGES>
__global__ void __launch_bounds__(256, 1)
tp_gemm(const float* __restrict__ W0, const float* __restrict__ W1,
        const float* __restrict__ T0, const float* __restrict__ T1,
        float* __restrict__ out, int outBase, int ldw) {
    constexpr int BK = 16;
    constexpr int NM16 = MROWS / 16;
    constexpr int AST = BK * MROWS;             // floats per A stage (contiguous)
    constexpr int BNP = BN + 8;
    constexpr int KTILES = KDIM / BK;           // 256
    constexpr int NTILES = NPATHS * KTILES;
    constexpr int LA = (AST / 4) / 256;         // float4 per thread (A); exact
    constexpr int NB4 = BK * BN / 4;            // float4 per stage (B): 256 or 128

    extern __shared__ float smem[];
    float* As = smem;                           // [STAGES][AST]
    float* Bs = smem + STAGES * AST;            // [STAGES][BK][BNP]

    const int tid = threadIdx.x;
    const int n0 = blockIdx.x * BN;

    const int warp = tid >> 5, lane = tid & 31;
    const int wm = warp & 3, wn = warp >> 2;       // 4x2 warp grid
    constexpr int MW = MROWS / 4;                  // warp m extent
    constexpr int NWT = BN / 2;                    // warp n extent
    constexpr int MT = MW / 16;
    constexpr int NT = NWT / 8;
    const int g = lane >> 2, tg = lane & 3;        // groupID, tid-in-group
    const int gxl = g ^ (tg << 1);                 // swizzled m-slot

    float acc[MT][NT][4];
#pragma unroll
    for (int a = 0; a < MT; a++)
#pragma unroll
        for (int b = 0; b < NT; b++)
#pragma unroll
            for (int i = 0; i < 4; i++) acc[a][b][i] = 0.f;

    // issue cp.async loads (A tile from T, B tile from W) for tile tn
    auto issue_tile = [&](int tn) {
        const float* Tp = (NPATHS == 2 && tn >= KTILES) ? T1 : T0;
        const float* Wp = (NPATHS == 2 && tn >= KTILES) ? W1 : W0;
        int tk = tn & (KTILES - 1);
        int st = tn % STAGES;
        float* Ad = As + st * AST;
        float* Bd = Bs + st * (BK * BNP);
        const float* Asrc = Tp + (size_t)tk * AST;
#pragma unroll
        for (int i = 0; i < LA; i++) {
            int e = (tid + i * 256) * 4;
            unsigned sa = (unsigned)__cvta_generic_to_shared(Ad + e);
            asm volatile("cp.async.cg.shared.global [%0], [%1], 16;\n"
                         :: "r"(sa), "l"(Asrc + e));
        }
        int k0 = tk * BK;
        if (NB4 >= 256) {
#pragma unroll
            for (int i = 0; i < NB4 / 256; i++) {
                int e = tid + i * 256;
                int kk = e / (BN / 4);
                int j = e - kk * (BN / 4);
                unsigned sb = (unsigned)__cvta_generic_to_shared(Bd + kk * BNP + j * 4);
                asm volatile("cp.async.cg.shared.global [%0], [%1], 16;\n"
                             :: "r"(sb), "l"(Wp + (size_t)(k0 + kk) * ldw + n0 + j * 4));
            }
        } else {
            if (tid < NB4) {
                int kk = tid / (BN / 4);
                int j = tid - kk * (BN / 4);
                unsigned sb = (unsigned)__cvta_generic_to_shared(Bd + kk * BNP + j * 4);
                asm volatile("cp.async.cg.shared.global [%0], [%1], 16;\n"
                             :: "r"(sb), "l"(Wp + (size_t)(k0 + kk) * ldw + n0 + j * 4));
            }
        }
        asm volatile("cp.async.commit_group;\n" ::: "memory");
    };

    // ---- prologue: fill STAGES-1 stages ----
#pragma unroll
    for (int s = 0; s < STAGES - 1; ++s) issue_tile(s);

#pragma unroll 1
    for (int t = 0; t < NTILES; ++t) {
        asm volatile("cp.async.wait_group %0;\n" :: "n"(STAGES - 2) : "memory");
        __syncthreads();

        if (t + STAGES - 1 < NTILES) issue_tile(t + STAGES - 1);

        const float* A = As + (t % STAGES) * AST;
        const float* B = Bs + (t % STAGES) * (BK * BNP);
#pragma unroll
        for (int kh = 0; kh < 2; kh++) {           // k half-groups of 8
            int kk = kh * 8;
            uint32_t bf[NT][2];
#pragma unroll
            for (int nt = 0; nt < NT; nt++) {
                int col = wn * NWT + nt * 8 + g;
                bf[nt][0] = f2tf32(B[(kk + tg) * BNP + col]);
                bf[nt][1] = f2tf32(B[(kk + tg + 4) * BNP + col]);
            }
            const float* Ak = A + (((kh * 4 + tg) * NM16) * 8 + gxl) * 4;
#pragma unroll
            for (int mt = 0; mt < MT; mt++) {
                int mb16 = wm * MT + mt;
                const float4 av = *reinterpret_cast<const float4*>(Ak + mb16 * 32);
                uint32_t fa0 = __float_as_uint(av.x);
                uint32_t fa1 = __float_as_uint(av.y);
                uint32_t fa2 = __float_as_uint(av.z);
                uint32_t fa3 = __float_as_uint(av.w);
#pragma unroll
                for (int nt = 0; nt < NT; nt++) {
                    asm volatile(
                        "mma.sync.aligned.m16n8k8.row.col.f32.tf32.tf32.f32 "
                        "{%0,%1,%2,%3}, {%4,%5,%6,%7}, {%8,%9}, {%0,%1,%2,%3};\n"
                        : "+f"(acc[mt][nt][0]), "+f"(acc[mt][nt][1]),
                          "+f"(acc[mt][nt][2]), "+f"(acc[mt][nt][3])
                        : "r"(fa0), "r"(fa1), "r"(fa2), "r"(fa3),
                          "r"(bf[nt][0]), "r"(bf[nt][1]));
                }
            }
        }
    }

    // ---- epilogue ----
#pragma unroll
    for (int mt = 0; mt < MT; mt++) {
#pragma unroll
        for (int half = 0; half < 2; half++) {
            int m = wm * MW + mt * 16 + g + half * 8;
            int b = m & 127;
            int k = m >> 7;
            size_t base = (size_t)b * 65536 + (size_t)outBase + (size_t)k;
#pragma unroll
            for (int nt = 0; nt < NT; nt++) {
                int n = n0 + wn * NWT + nt * 8 + 2 * tg;
                out[base + (size_t)n * KOUT] = acc[mt][nt][half * 2 + 0];
                out[base + (size_t)(n + 1) * KOUT] = acc[mt][nt][half * 2 + 1];
            }
        }
    }
}

// ---------------------------------------------------------------------
// Host: exact replica of the reference CG / real-basis math (fp64)
// ---------------------------------------------------------------------
static double factd(int n) { double r = 1.0; for (int i = 2; i <= n; i++) r *= i; return r; }

static void cg_complex_host(int l1, int l2, int l3, double* C) {
    int d1 = 2 * l1 + 1, d2 = 2 * l2 + 1, d3 = 2 * l3 + 1;
    for (int i = 0; i < d1 * d2 * d3; i++) C[i] = 0.0;
    for (int m1 = -l1; m1 <= l1; m1++)
        for (int m2 = -l2; m2 <= l2; m2++) {
            int m3 = m1 + m2;
            if (m3 < -l3 || m3 > l3) continue;
            double pref = std::sqrt((2 * l3 + 1) * factd(l3 + l1 - l2) * factd(l3 - l1 + l2) *
                                    factd(l1 + l2 - l3) / factd(l1 + l2 + l3 + 1));
            pref *= std::sqrt(factd(l3 + m3) * factd(l3 - m3) * factd(l1 - m1) *
                              factd(l1 + m1) * factd(l2 - m2) * factd(l2 + m2));
            double s = 0.0;
            for (int k = 0; k <= l1 + l2 - l3; k++) {
                int d[5] = {l1 + l2 - l3 - k, l1 - m1 - k, l2 + m2 - k,
                            l3 - l2 + m1 + k, l3 - l1 - m2 + k};
                bool ok = true;
                for (int q = 0; q < 5; q++) if (d[q] < 0) ok = false;
                if (!ok) continue;
                double den = factd(k);
                for (int q = 0; q < 5; q++) den *= factd(d[q]);
                s += ((k & 1) ? -1.0 : 1.0) / den;
            }
            C[((m1 + l1) * d2 + (m2 + l2)) * d3 + (m3 + l3)] = pref * s;
        }
}

static void real_basis_host(int l, std::complex<double>* U) {
    int d = 2 * l + 1;
    for (int i = 0; i < d * d; i++) U[i] = 0.0;
    double s2 = 1.0 / std::sqrt(2.0);
    for (int m = -l; m <= l; m++) {
        int r = m + l;
        if (m > 0) {
            U[r * d + (-m + l)] = s2;
            U[r * d + (m + l)] = ((m & 1) ? -1.0 : 1.0) * s2;
        } else if (m == 0) {
            U[r * d + l] = 1.0;
        } else {
            int a = -m;
            U[r * d + (-a + l)] = std::complex<double>(0.0, s2);
            U[r * d + (a + l)] = std::complex<double>(0.0, -(((a & 1) ? -1.0 : 1.0) * s2));
        }
    }
}

static void w3j_host(int l1, int l2, int l3, float* out) {
    int d1 = 2 * l1 + 1, d2 = 2 * l2 + 1, d3 = 2 * l3 + 1;
    double Cc[125];
    cg_complex_host(l1, l2, l3, Cc);
    std::complex<double> U1[25], U2[25], U3[25];
    real_basis_host(l1, U1); real_basis_host(l2, U2); real_basis_host(l3, U3);
    double Cr[125], Ci[125];
    for (int i = 0; i < d1; i++)
        for (int j = 0; j < d2; j++)
            for (int k = 0; k < d3; k++) {
                std::complex<double> acc(0.0, 0.0);
                for (int m = 0; m < d1; m++)
                    for (int n = 0; n < d2; n++)
                        for (int p = 0; p < d3; p++)
                            acc += U1[i * d1 + m] * U2[j * d2 + n] *
                                   std::conj(U3[k * d3 + p]) * Cc[(m * d2 + n) * d3 + p];
                Cr[(i * d2 + j) * d3 + k] = acc.real();
                Ci[(i * d2 + j) * d3 + k] = acc.imag();
            }
    double nr = 0.0, ni = 0.0;
    int tot = d1 * d2 * d3;
    for (int i = 0; i < tot; i++) { nr += Cr[i] * Cr[i]; ni += Ci[i] * Ci[i]; }
    const double* S = (nr >= ni) ? Cr : Ci;
    double nn = std::sqrt((nr >= ni) ? nr : ni);
    for (int i = 0; i < tot; i++) out[i] = (float)(S[i] / nn);
}

// ---------------------------------------------------------------------
extern "C" void kernel_launch(void* const* d_in, const int* in_sizes, int n_in,
                              void* d_out, int out_size) {
    const float* x1 = (const float*)d_in[0];
    const float* x2 = (const float*)d_in[1];
    const float* w1 = (const float*)d_in[2];
    const float* w2 = (const float*)d_in[3];
    const float* w3 = (const float*)d_in[4];
    const float* w4 = (const float*)d_in[5];
    const float* w5 = (const float*)d_in[6];
    const float* w6 = (const float*)d_in[7];
    float* out = (float*)d_out;

    Coup c;
    float tmp[64];
    w3j_host(0, 0, 0, tmp); c.w000 = tmp[0];
    w3j_host(1, 1, 0, tmp); memcpy(c.w110, tmp, 9 * sizeof(float));
    w3j_host(0, 1, 1, tmp); memcpy(c.w011, tmp, 9 * sizeof(float));
    w3j_host(1, 0, 1, tmp); memcpy(c.w101, tmp, 9 * sizeof(float));
    w3j_host(1, 1, 1, tmp); memcpy(c.w111, tmp, 27 * sizeof(float));
    w3j_host(1, 1, 2, tmp); memcpy(c.w112, tmp, 45 * sizeof(float));
    c.s0 = sqrtf(1.0f / 8192.0f);
    c.s1 = sqrtf(3.0f / 8192.0f);
    c.s1e = sqrtf(3.0f / 4096.0f);
    c.s2e = sqrtf(5.0f / 4096.0f);

    float* T = nullptr;
    cudaGetSymbolAddress((void**)&T, g_T);

    // smem bytes: STAGES * (16*MROWS + 16*(BN+8)) * 4
    constexpr int SM_G0 = 12 * (2048 + 1152) * 4;   // 153600
    constexpr int SM_G1 = 7 * (6144 + 1152) * 4;    // 204288
    constexpr int SM_G2 = 8 * (6144 + 640) * 4;     // 217088
    constexpr int SM_G3 = 5 * (10240 + 640) * 4;    // 217600

    cudaFuncSetAttribute((const void*)tp_gemm<128, 64, 2, 1, 12>,
                         cudaFuncAttributeMaxDynamicSharedMemorySize, SM_G0);
    cudaFuncSetAttribute((const void*)tp_gemm<384, 64, 2, 3, 7>,
                         cudaFuncAttributeMaxDynamicSharedMemorySize, SM_G1);
    cudaFuncSetAttribute((const void*)tp_gemm<384, 32, 1, 3, 8>,
                         cudaFuncAttributeMaxDynamicSharedMemorySize, SM_G2);
    cudaFuncSetAttribute((const void*)tp_gemm<640, 32, 1, 5, 5>,
                         cudaFuncAttributeMaxDynamicSharedMemorySize, SM_G3);

    phaseA_kernel<<<2048, 256>>>(x1, x2, c);

    // G0: o0 (b, 8192x0e) at offset 0
    tp_gemm<128, 64, 2, 1, 12><<<128, 256, SM_G0>>>(w1, w2, T + OFF_T1, T + OFF_T2, out, 0, 8192);
    // G1: o1 (b, 8192x1o) at offset 8192
    tp_gemm<384, 64, 2, 3, 7><<<128, 256, SM_G1>>>(w3, w4, T + OFF_T3, T + OFF_T4, out, 8192, 8192);
    // G2: o1e (b, 4096x1e) at offset 32768
    tp_gemm<384, 32, 1, 3, 8><<<128, 256, SM_G2>>>(w5, w5, T + OFF_T5, T + OFF_T5, out, 32768, 4096);
    // G3: o2e (b, 4096x2e) at offset 45056
    tp_gemm<640, 32, 1, 5, 5><<<128, 256, SM_G3>>>(w6, w6, T + OFF_T6, T + OFF_T6, out, 45056, 4096);
}